// round 3
// baseline (speedup 1.0000x reference)
#include <cuda_runtime.h>
#include <cuda_fp16.h>
#include <cuda_bf16.h>

// Problem constants
#define TT 256
#define BB 1024
#define OBS 128
#define LS 128
#define HH 128
#define NA 18
#define MROWS (TT*BB)          // 262144

// ---------------------------------------------------------------------------
// Scratch (device globals; no cudaMalloc allowed)
// ---------------------------------------------------------------------------
__device__ float g_h1[(size_t)MROWS * 128];   // encoder layer-1 out
__device__ float g_h2[(size_t)MROWS * 32];    // encoder layer-2 out
__device__ float g_h3[(size_t)MROWS * 128];   // encoder layer-3 out
__device__ float g_Z [(size_t)MROWS * 512];   // precomputed input gates + biases

// ---------------------------------------------------------------------------
// Fast nonlinearities (MUFU EX2/RCP; fma pipe stays free for the matvec)
// ---------------------------------------------------------------------------
__device__ __forceinline__ float sigm_fast(float x) {
    x = fminf(fmaxf(x, -30.f), 30.f);
    return __fdividef(1.f, 1.f + __expf(-x));
}
__device__ __forceinline__ float tanh_fast(float x) {
    x = fminf(fmaxf(x, -15.f), 15.f);
    float e = __expf(-2.f * x);
    return __fdividef(1.f - e, 1.f + e);
}

// ---------------------------------------------------------------------------
// Generic tiled GEMM:  C[M][N] = act( A[M][K] @ W[N][K]^T + bias1 (+ bias2) )
// Tile: 64 rows x NT cols, 256 threads, whole K resident in smem (K <= 128).
// ---------------------------------------------------------------------------
template<int KT, int NT, bool RELU>
__global__ void __launch_bounds__(256, 2) gemm_kernel(
    const float* __restrict__ A, const float* __restrict__ W,
    const float* __restrict__ bias1, const float* __restrict__ bias2,
    float* __restrict__ C, int N)
{
    constexpr int AP  = 68;        // padded leading dim for As[k][r]
    constexpr int BP  = NT + 4;    // padded leading dim for Bs[k][j]
    constexpr int KQ  = KT / 4;
    constexpr int CPT = NT / 32;   // cols per thread (4 or 1)

    extern __shared__ float smg[];
    float* As = smg;               // KT * AP
    float* Bs = smg + KT * AP;     // KT * BP

    const int  tid  = threadIdx.x;
    const long row0 = (long)blockIdx.x * 64;
    const int  c0   = blockIdx.y * NT;

    // Load A tile transposed (As[k][r]); stores conflict-free (r fastest)
    for (int idx = tid; idx < KQ * 64; idx += 256) {
        int kq = idx / 64, r = idx % 64;
        float4 v = *reinterpret_cast<const float4*>(A + (row0 + r) * KT + kq * 4);
        As[(kq*4+0)*AP + r] = v.x;
        As[(kq*4+1)*AP + r] = v.y;
        As[(kq*4+2)*AP + r] = v.z;
        As[(kq*4+3)*AP + r] = v.w;
    }
    // Load W tile transposed (Bs[k][j])
    for (int idx = tid; idx < KQ * NT; idx += 256) {
        int kq = idx / NT, jj = idx % NT;
        float4 v = *reinterpret_cast<const float4*>(W + (long)(c0 + jj) * KT + kq * 4);
        Bs[(kq*4+0)*BP + jj] = v.x;
        Bs[(kq*4+1)*BP + jj] = v.y;
        Bs[(kq*4+2)*BP + jj] = v.z;
        Bs[(kq*4+3)*BP + jj] = v.w;
    }
    __syncthreads();

    const int tx = tid & 31, ty = tid >> 5;
    float acc[8][CPT];
    #pragma unroll
    for (int i = 0; i < 8; ++i)
        #pragma unroll
        for (int c = 0; c < CPT; ++c) acc[i][c] = 0.f;

    #pragma unroll 8
    for (int k = 0; k < KT; ++k) {
        const float* ar = &As[k * AP + ty * 8];
        float4 a0 = *reinterpret_cast<const float4*>(ar);
        float4 a1 = *reinterpret_cast<const float4*>(ar + 4);
        float a[8] = {a0.x, a0.y, a0.z, a0.w, a1.x, a1.y, a1.z, a1.w};
        float bb[CPT];
        if constexpr (CPT == 4) {
            float4 bv = *reinterpret_cast<const float4*>(&Bs[k * BP + tx * 4]);
            bb[0] = bv.x; bb[1] = bv.y; bb[2] = bv.z; bb[3] = bv.w;
        } else {
            bb[0] = Bs[k * BP + tx];
        }
        #pragma unroll
        for (int i = 0; i < 8; ++i)
            #pragma unroll
            for (int c = 0; c < CPT; ++c)
                acc[i][c] = fmaf(a[i], bb[c], acc[i][c]);
    }

    // Epilogue
    if constexpr (CPT == 4) {
        float bsum[4];
        #pragma unroll
        for (int c = 0; c < 4; ++c) {
            int col = c0 + tx * 4 + c;
            bsum[c] = bias1[col] + (bias2 ? bias2[col] : 0.f);
        }
        #pragma unroll
        for (int i = 0; i < 8; ++i) {
            long row = row0 + ty * 8 + i;
            float4 o;
            o.x = acc[i][0] + bsum[0];
            o.y = acc[i][1] + bsum[1];
            o.z = acc[i][2] + bsum[2];
            o.w = acc[i][3] + bsum[3];
            if (RELU) {
                o.x = fmaxf(o.x, 0.f); o.y = fmaxf(o.y, 0.f);
                o.z = fmaxf(o.z, 0.f); o.w = fmaxf(o.w, 0.f);
            }
            *reinterpret_cast<float4*>(C + row * N + c0 + tx * 4) = o;
        }
    } else {
        int col = c0 + tx;
        float bsum = bias1[col] + (bias2 ? bias2[col] : 0.f);
        #pragma unroll
        for (int i = 0; i < 8; ++i) {
            long row = row0 + ty * 8 + i;
            float v = acc[i][0] + bsum;
            if (RELU) v = fmaxf(v, 0.f);
            C[row * N + col] = v;
        }
    }
}

// ---------------------------------------------------------------------------
// Persistent LSTM recurrence + heads.
// 148 CTAs x 512 threads. Each CTA owns <=7 batch lanes for all 256 steps.
// Whh resident in smem as fp16 (fp32 h, fp32 accumulate).
// Thread j (0..511) computes gate j for all its batch lanes.
// ---------------------------------------------------------------------------
// smem byte offsets
#define OFF_WSH   0                        // 512*128 half  = 131072
#define OFF_HBUF  131072                   // 7*128 f32     =   3584
#define OFF_CBUF  134656                   //               =   3584
#define OFF_GBUF  138240                   // 512*8 f32     =  16384
#define OFF_WAC   154624                   // 19*132 f32    =  10048 (pad)
#define OFF_BAC   164672                   // 19 f32        =     80 (pad)
#define OFF_MS    164752                   // 7 f32         =     32 (pad)
#define SMEM_LSTM 164784

__global__ void __launch_bounds__(512, 1) lstm_kernel(
    const float* __restrict__ Z,    const float* __restrict__ done,
    const float* __restrict__ h0,   const float* __restrict__ c0,
    const float* __restrict__ Whh,
    const float* __restrict__ Wa,   const float* __restrict__ ba,
    const float* __restrict__ Wc,   const float* __restrict__ bc,
    float* __restrict__ out)
{
    extern __shared__ char smraw[];
    __half* wsh  = reinterpret_cast<__half*>(smraw + OFF_WSH);
    float*  hbuf = reinterpret_cast<float*>(smraw + OFF_HBUF);
    float*  cbuf = reinterpret_cast<float*>(smraw + OFF_CBUF);
    float*  gbuf = reinterpret_cast<float*>(smraw + OFF_GBUF);
    float*  WaCs = reinterpret_cast<float*>(smraw + OFF_WAC);
    float*  bac  = reinterpret_cast<float*>(smraw + OFF_BAC);
    float*  ms   = reinterpret_cast<float*>(smraw + OFF_MS);

    const int tid = threadIdx.x;
    const int cta = blockIdx.x;
    // batch distribution: CTAs 0..135 -> 7 lanes, 136..147 -> 6 lanes
    const int gb0 = (cta < 136) ? cta * 7 : 952 + (cta - 136) * 6;
    const int nb  = (cta < 136) ? 7 : 6;

    // --- Setup: Whh -> fp16 smem, interleaved layout: [(k/4)][j][k%4]
    for (int idx = tid; idx < 512 * 128; idx += 512) {
        int jj = idx >> 7, k = idx & 127;
        wsh[((k >> 2) << 11) + (jj << 2) + (k & 3)] = __float2half(Whh[idx]);
    }
    // --- h0/c0 into smem (unused lanes zeroed)
    for (int idx = tid; idx < 7 * 128; idx += 512) {
        int b = idx >> 7, u = idx & 127;
        hbuf[idx] = (b < nb) ? h0[(gb0 + b) * HH + u] : 0.f;
        cbuf[idx] = (b < nb) ? c0[(gb0 + b) * HH + u] : 0.f;
    }
    // --- combined head weights (Wa rows 0..17, Wc row 18), padded ld=132
    for (int idx = tid; idx < 19 * 128; idx += 512) {
        int a = idx >> 7, k = idx & 127;
        WaCs[a * 132 + k] = (a < 18) ? Wa[a * 128 + k] : Wc[k];
    }
    if (tid < 19) bac[tid] = (tid < 18) ? ba[tid] : bc[0];
    if (tid < 7)  ms[tid]  = (tid < nb) ? (1.f - done[gb0 + tid]) : 1.f;
    __syncthreads();

    const int j    = tid;          // gate index 0..511
    const int type = j >> 7;       // 0=i,1=f,2=g,3=o  (warp-uniform)

    for (int t = 0; t < TT; ++t) {
        // ---- phase 1: done-mask h,c (mask for step t, prefetched) ----
        for (int idx = tid; idx < nb * 128; idx += 512) {
            float m = ms[idx >> 7];
            hbuf[idx] *= m;
            cbuf[idx] *= m;
        }
        __syncthreads();

        // ---- phase 2: matvec gates = Whh @ h  (+ Z, prefetched up front)
        float zr[7];
        const long zbase = ((long)t * BB + gb0) * 512 + j;
        #pragma unroll
        for (int b = 0; b < 7; ++b)
            zr[b] = (b < nb) ? Z[zbase + (long)b * 512] : 0.f;
        float dn = 0.f;
        if (tid < 7)
            dn = (tid < nb && t < TT - 1) ? done[(t + 1) * BB + gb0 + tid] : 0.f;

        float acc[7] = {0.f, 0.f, 0.f, 0.f, 0.f, 0.f, 0.f};
        #pragma unroll 4
        for (int k4 = 0; k4 < 32; ++k4) {
            uint2 wr = *reinterpret_cast<const uint2*>(wsh + (k4 << 11) + (j << 2));
            float2 w01 = __half22float2(*reinterpret_cast<const __half2*>(&wr.x));
            float2 w23 = __half22float2(*reinterpret_cast<const __half2*>(&wr.y));
            #pragma unroll
            for (int b = 0; b < 7; ++b) {
                float4 hv = *reinterpret_cast<const float4*>(&hbuf[b * 128 + (k4 << 2)]);
                acc[b] = fmaf(w01.x, hv.x, acc[b]);
                acc[b] = fmaf(w01.y, hv.y, acc[b]);
                acc[b] = fmaf(w23.x, hv.z, acc[b]);
                acc[b] = fmaf(w23.y, hv.w, acc[b]);
            }
        }
        #pragma unroll
        for (int b = 0; b < 7; ++b) {
            float v = acc[b] + zr[b];
            float gv = (type == 2) ? tanh_fast(v) : sigm_fast(v);
            gbuf[(j << 3) + b] = gv;
        }
        if (tid < 7) ms[tid] = 1.f - dn;   // mask for next step
        __syncthreads();

        // ---- phase 3: c,h update ----
        for (int idx = tid; idx < nb * 128; idx += 512) {
            int b = idx & 127 ? (idx >> 7) : (idx >> 7);  // b = idx>>7
            int u = idx & 127;
            int g8 = (u << 3) + (idx >> 7);
            float iv = gbuf[g8];
            float fv = gbuf[g8 + 1024];
            float gg = gbuf[g8 + 2048];
            float ov = gbuf[g8 + 3072];
            float cv = fmaf(fv, cbuf[idx], iv * gg);
            float hv = ov * tanh_fast(cv);
            cbuf[idx] = cv;
            hbuf[idx] = hv;
            (void)b;
        }
        __syncthreads();

        // ---- phase 4: heads (logits + value), write output row ----
        if (tid < nb * 19) {
            int b = tid / 19, a = tid - b * 19;
            float s0 = 0.f, s1 = 0.f;
            #pragma unroll 4
            for (int k8 = 0; k8 < 16; ++k8) {
                float4 w0 = *reinterpret_cast<const float4*>(&WaCs[a * 132 + k8 * 8]);
                float4 w1 = *reinterpret_cast<const float4*>(&WaCs[a * 132 + k8 * 8 + 4]);
                float4 h0v = *reinterpret_cast<const float4*>(&hbuf[b * 128 + k8 * 8]);
                float4 h1v = *reinterpret_cast<const float4*>(&hbuf[b * 128 + k8 * 8 + 4]);
                s0 = fmaf(w0.x, h0v.x, s0); s0 = fmaf(w0.y, h0v.y, s0);
                s0 = fmaf(w0.z, h0v.z, s0); s0 = fmaf(w0.w, h0v.w, s0);
                s1 = fmaf(w1.x, h1v.x, s1); s1 = fmaf(w1.y, h1v.y, s1);
                s1 = fmaf(w1.z, h1v.z, s1); s1 = fmaf(w1.w, h1v.w, s1);
            }
            out[((long)t * BB + gb0 + b) * 19 + a] = s0 + s1 + bac[a];
        }
        __syncthreads();
    }
}

// ---------------------------------------------------------------------------
// Host launcher
// ---------------------------------------------------------------------------
extern "C" void kernel_launch(void* const* d_in, const int* in_sizes, int n_in,
                              void* d_out, int out_size)
{
    const float* x    = (const float*)d_in[0];
    const float* done = (const float*)d_in[1];
    const float* h0   = (const float*)d_in[2];
    const float* c0   = (const float*)d_in[3];
    const float* W1   = (const float*)d_in[4];
    const float* b1   = (const float*)d_in[5];
    const float* W2   = (const float*)d_in[6];
    const float* b2   = (const float*)d_in[7];
    const float* W3   = (const float*)d_in[8];
    const float* b3   = (const float*)d_in[9];
    const float* Wih  = (const float*)d_in[10];
    const float* Whh  = (const float*)d_in[11];
    const float* bih  = (const float*)d_in[12];
    const float* bhh  = (const float*)d_in[13];
    const float* Wa   = (const float*)d_in[14];
    const float* ba   = (const float*)d_in[15];
    const float* Wc   = (const float*)d_in[16];
    const float* bc   = (const float*)d_in[17];
    float* out = (float*)d_out;

    float *h1p, *h2p, *h3p, *Zp;
    cudaGetSymbolAddress((void**)&h1p, g_h1);
    cudaGetSymbolAddress((void**)&h2p, g_h2);
    cudaGetSymbolAddress((void**)&h3p, g_h3);
    cudaGetSymbolAddress((void**)&Zp,  g_Z);

    const int S_128_128 = (128 * 68 + 128 * 132) * 4;  // 102400
    const int S_128_32  = (128 * 68 + 128 * 36)  * 4;  //  53248
    const int S_32_128  = (32  * 68 + 32  * 132) * 4;  //  25600

    cudaFuncSetAttribute(gemm_kernel<128, 128, true>,
                         cudaFuncAttributeMaxDynamicSharedMemorySize, S_128_128);
    cudaFuncSetAttribute(gemm_kernel<128, 128, false>,
                         cudaFuncAttributeMaxDynamicSharedMemorySize, S_128_128);
    cudaFuncSetAttribute(gemm_kernel<128, 32, true>,
                         cudaFuncAttributeMaxDynamicSharedMemorySize, S_128_32);
    cudaFuncSetAttribute(gemm_kernel<32, 128, true>,
                         cudaFuncAttributeMaxDynamicSharedMemorySize, S_32_128);
    cudaFuncSetAttribute(lstm_kernel,
                         cudaFuncAttributeMaxDynamicSharedMemorySize, SMEM_LSTM);

    const int NT_ROW = MROWS / 64;  // 4096 row tiles

    // Encoder
    gemm_kernel<128, 128, true><<<dim3(NT_ROW, 1), 256, S_128_128>>>(
        x,   W1, b1, nullptr, h1p, 128);
    gemm_kernel<128, 32, true><<<dim3(NT_ROW, 1), 256, S_128_32>>>(
        h1p, W2, b2, nullptr, h2p, 32);
    gemm_kernel<32, 128, true><<<dim3(NT_ROW, 1), 256, S_32_128>>>(
        h2p, W3, b3, nullptr, h3p, 128);
    // Input projection: Z = hid @ Wih^T + bih + bhh   (N = 512, 4 col tiles)
    gemm_kernel<128, 128, false><<<dim3(NT_ROW, 4), 256, S_128_128>>>(
        h3p, Wih, bih, bhh, Zp, 512);

    // Recurrence + heads
    lstm_kernel<<<148, 512, SMEM_LSTM>>>(
        Zp, done, h0, c0, Whh, Wa, ba, Wc, bc, out);
}